// round 8
// baseline (speedup 1.0000x reference)
#include <cuda_runtime.h>

// Sinkhorn distance, N=M=4096, D=2, P=1, eps=0.1, 50 iterations.
// Persistent kernel + global software barrier (round-2 skeleton).
// Iterations run in the LINEAR (exponential) domain with the factorized
// min-trick: 2^{v - |dx|s - |dy|s} = min(P0*e0, P0r*e1) * min(P1*f0, P1r*f1)
// -> zero MUFU ops in the inner loop (was the 8192 cyc/SMSP floor).
// Fixed 2^{±coord*s} tables built once; per-pass staging = 2 FMUL per j.

#define NN      4096
#define NCTA    128
#define NT      1024
#define NWARP   32
#define RPC     32
#define PPW     64          // j-pairs per warp per pass
#define ITERS   50

#define SCALEF  14.426950408889634f    // log2(e)/eps
#define MUVAL   0.000244150625f        // 1/4096 + 1e-8
#define LMU2    (-11.9999409054f)      // log2(MUVAL)

typedef unsigned long long ull;

__device__ float4 gTx0[NN / 2], gTx1[NN / 2];   // {2^-C(2p),2^-C(2p+1),2^+C(2p),2^+C(2p+1)}
__device__ float4 gTy0[NN / 2], gTy1[NN / 2];
__device__ float g_u_exp[NN], g_v_exp[NN];
__device__ float g_u_log[NN], g_v_log[NN];
__device__ float g_cost[NCTA];
__device__ unsigned int g_costcnt;
__device__ unsigned int sk_bar_count;
__device__ volatile unsigned int sk_bar_phase;

__device__ __forceinline__ float ex2f(float v) {
    float r; asm("ex2.approx.f32 %0, %1;" : "=f"(r) : "f"(v)); return r;
}
__device__ __forceinline__ float lg2f(float v) {
    float r; asm("lg2.approx.f32 %0, %1;" : "=f"(r) : "f"(v)); return r;
}
__device__ __forceinline__ float rcpf(float v) {
    float r; asm("rcp.approx.f32 %0, %1;" : "=f"(r) : "f"(v)); return r;
}
__device__ __forceinline__ ull fadd2(ull a, ull b) {
    ull r; asm("add.rn.f32x2 %0, %1, %2;" : "=l"(r) : "l"(a), "l"(b)); return r;
}
__device__ __forceinline__ ull fmul2(ull a, ull b) {
    ull r; asm("mul.rn.f32x2 %0, %1, %2;" : "=l"(r) : "l"(a), "l"(b)); return r;
}
__device__ __forceinline__ ull ffma2(ull a, ull b, ull c) {
    ull r; asm("fma.rn.f32x2 %0, %1, %2, %3;" : "=l"(r) : "l"(a), "l"(b), "l"(c)); return r;
}
__device__ __forceinline__ ull pk(float lo, float hi) {
    ull r; asm("mov.b64 %0, {%1, %2};" : "=l"(r) : "f"(lo), "f"(hi)); return r;
}
__device__ __forceinline__ void upk(ull v, float& lo, float& hi) {
    asm("mov.b64 {%0, %1}, %2;" : "=f"(lo), "=f"(hi) : "l"(v));
}

__device__ __forceinline__ void grid_barrier(unsigned int target) {
    __threadfence();
    __syncthreads();
    if (threadIdx.x == 0) {
        unsigned int t = atomicAdd(&sk_bar_count, 1u);
        if (t == NCTA - 1) {
            sk_bar_count = 0;
            __threadfence();
            sk_bar_phase = target;
        } else {
            while (sk_bar_phase < target) { }
        }
    }
    __syncthreads();
}

__global__ void sk_init_kernel(const float* __restrict__ x, const float* __restrict__ y) {
    int t = blockIdx.x * blockDim.x + threadIdx.x;
    if (t == 0) { sk_bar_count = 0; sk_bar_phase = 0; g_costcnt = 0; }
    if (t < NN / 2) {
        float4 a = ((const float4*)x)[t];   // {x0_2t, x1_2t, x0_2t+1, x1_2t+1}
        gTx0[t] = make_float4(ex2f(-SCALEF * a.x), ex2f(-SCALEF * a.z),
                              ex2f( SCALEF * a.x), ex2f( SCALEF * a.z));
        gTx1[t] = make_float4(ex2f(-SCALEF * a.y), ex2f(-SCALEF * a.w),
                              ex2f( SCALEF * a.y), ex2f( SCALEF * a.w));
        float4 b = ((const float4*)y)[t];
        gTy0[t] = make_float4(ex2f(-SCALEF * b.x), ex2f(-SCALEF * b.z),
                              ex2f( SCALEF * b.x), ex2f( SCALEF * b.z));
        gTy1[t] = make_float4(ex2f(-SCALEF * b.y), ex2f(-SCALEF * b.w),
                              ex2f( SCALEF * b.y), ex2f( SCALEF * b.w));
    }
    for (int i = t; i < NN; i += gridDim.x * blockDim.x) {
        g_v_exp[i] = 1.f;    // 2^{v=0}
        g_v_log[i] = 0.f;
    }
}

// acc += min(P0*e01, P0r*e23) * min(P1*f01, P1r*f23)   (packed, 2 elems)
__device__ __forceinline__ void sk_min_step(ull& acc, float4 e, float4 f,
                                            ull P0, ull P0r, ull P1, ull P1r) {
    ull t0 = fmul2(P0,  pk(e.x, e.y));
    ull t1 = fmul2(P0r, pk(e.z, e.w));
    float a, b, c, d;
    upk(t0, a, b); upk(t1, c, d);
    float m0l = fminf(a, c), m0h = fminf(b, d);
    ull t2 = fmul2(P1,  pk(f.x, f.y));
    ull t3 = fmul2(P1r, pk(f.z, f.w));
    upk(t2, a, b); upk(t3, c, d);
    float m1l = fminf(a, c), m1h = fminf(b, d);
    acc = ffma2(pk(m0l, m0h), pk(m1l, m1h), acc);
}

__global__ void __launch_bounds__(NT, 1)
sk_persist_kernel(const float* __restrict__ x, const float* __restrict__ y,
                  float* __restrict__ out) {
    extern __shared__ float4 sm[];
    float4* fx0 = sm;               // fixed 2^{±X0s}, pair-interleaved (32KB)
    float4* fx1 = sm + 2048;        // fixed 2^{±X1s} (32KB)
    float4* fy0 = sm + 4096;        // fixed 2^{±Y0s} (32KB)
    float4* fy1 = sm + 6144;        // fixed 2^{±Y1s} (32KB)
    float4* wex = sm + 8192;        // per-pass {g0,g0,g1,g1} from U (32KB)
    float4* wey = sm + 10240;       // per-pass {e0,e0,e1,e1} from V (32KB)
    __shared__ float part[NWARP * 33];
    __shared__ float red[NWARP];

    const int tid  = threadIdx.x;
    const int lane = tid & 31;
    const int wid  = tid >> 5;
    const int cta  = blockIdx.x;
    const int rbase = cta * RPC;

    // Stage fixed tables (L2-resident, shared by all CTAs).
    for (int i = tid; i < NN / 2; i += NT) {
        fx0[i] = __ldcg(&gTx0[i]);
        fx1[i] = __ldcg(&gTx1[i]);
        fy0[i] = __ldcg(&gTy0[i]);
        fy1[i] = __ldcg(&gTy1[i]);
    }
    __syncthreads();

    // Per-lane row constants (lane owns row rbase+lane).
    const int myrow = rbase + lane;
    ull P0, P0r, P1, P1r, Q0, Q0r, Q1, Q1r;
    {
        int pr = myrow >> 1, pa = myrow & 1;
        float4 a = fx0[pr], b = fx1[pr];
        float p0  = pa ? a.w : a.z, p0r = pa ? a.y : a.x;
        float p1  = pa ? b.w : b.z, p1r = pa ? b.y : b.x;
        P0 = pk(p0, p0); P0r = pk(p0r, p0r); P1 = pk(p1, p1); P1r = pk(p1r, p1r);
        float4 c = fy0[pr], d = fy1[pr];
        float q0  = pa ? c.w : c.z, q0r = pa ? c.y : c.x;
        float q1  = pa ? d.w : d.z, q1r = pa ? d.y : d.x;
        Q0 = pk(q0, q0); Q0r = pk(q0r, q0r); Q1 = pk(q1, q1); Q1r = pk(q1r, q1r);
    }

    unsigned int phase = 0;

    for (int it = 0; it < ITERS; ++it) {
        // ===== u pass: S_i = sum_j V_j * 2^{-C_ij~};  U_i = mu/S_i =====
        {
            float4 V4 = __ldcg((const float4*)g_v_exp + tid);   // j = 4t..4t+3
            float4 a = fy0[2 * tid], b = fy0[2 * tid + 1];
            wey[2 * tid]     = make_float4(a.x * V4.x, a.y * V4.y, a.z * V4.x, a.w * V4.y);
            wey[2 * tid + 1] = make_float4(b.x * V4.z, b.y * V4.w, b.z * V4.z, b.w * V4.w);
        }
        __syncthreads();
        {
            const float4* ep = wey + wid * PPW;
            const float4* fp = fy1 + wid * PPW;
            ull a0 = 0, a1 = 0, a2 = 0, a3 = 0;
            #pragma unroll 4
            for (int k = 0; k < PPW; k += 4) {
                sk_min_step(a0, ep[k + 0], fp[k + 0], P0, P0r, P1, P1r);
                sk_min_step(a1, ep[k + 1], fp[k + 1], P0, P0r, P1, P1r);
                sk_min_step(a2, ep[k + 2], fp[k + 2], P0, P0r, P1, P1r);
                sk_min_step(a3, ep[k + 3], fp[k + 3], P0, P0r, P1, P1r);
            }
            ull t = fadd2(fadd2(a0, a1), fadd2(a2, a3));
            float tl, th; upk(t, tl, th);
            part[wid * 33 + lane] = tl + th;
        }
        __syncthreads();
        {   // warp wid totals row rbase+wid
            float pv = part[lane * 33 + wid];
            #pragma unroll
            for (int o = 16; o > 0; o >>= 1) pv += __shfl_xor_sync(0xffffffffu, pv, o);
            if (lane == 0) {
                __stcg(&g_u_exp[rbase + wid], MUVAL * rcpf(pv));
                __stcg(&g_u_log[rbase + wid], LMU2 - lg2f(pv));
            }
        }
        grid_barrier(++phase);

        // ===== v pass: S_j = sum_i U_i * 2^{-C_ij~};  V_j = mu/S_j =====
        {
            float4 U4 = __ldcg((const float4*)g_u_exp + tid);
            float4 a = fx0[2 * tid], b = fx0[2 * tid + 1];
            wex[2 * tid]     = make_float4(a.x * U4.x, a.y * U4.y, a.z * U4.x, a.w * U4.y);
            wex[2 * tid + 1] = make_float4(b.x * U4.z, b.y * U4.w, b.z * U4.z, b.w * U4.w);
        }
        __syncthreads();
        {
            const float4* ep = wex + wid * PPW;
            const float4* fp = fx1 + wid * PPW;
            ull a0 = 0, a1 = 0, a2 = 0, a3 = 0;
            #pragma unroll 4
            for (int k = 0; k < PPW; k += 4) {
                sk_min_step(a0, ep[k + 0], fp[k + 0], Q0, Q0r, Q1, Q1r);
                sk_min_step(a1, ep[k + 1], fp[k + 1], Q0, Q0r, Q1, Q1r);
                sk_min_step(a2, ep[k + 2], fp[k + 2], Q0, Q0r, Q1, Q1r);
                sk_min_step(a3, ep[k + 3], fp[k + 3], Q0, Q0r, Q1, Q1r);
            }
            ull t = fadd2(fadd2(a0, a1), fadd2(a2, a3));
            float tl, th; upk(t, tl, th);
            part[wid * 33 + lane] = tl + th;
        }
        __syncthreads();
        {
            float pv = part[lane * 33 + wid];
            #pragma unroll
            for (int o = 16; o > 0; o >>= 1) pv += __shfl_xor_sync(0xffffffffu, pv, o);
            if (lane == 0) {
                __stcg(&g_v_exp[rbase + wid], MUVAL * rcpf(pv));
                __stcg(&g_v_log[rbase + wid], LMU2 - lg2f(pv));
            }
        }
        grid_barrier(++phase);
    }

    // ===== final: pi = 2^{ut_i + vt_j - s*ct}, C = ct, cost = sum(pi*C) =====
    // Repurpose wey as raw negated UNSCALED y coords, wex front as vt buffer.
    {
        float4 ya = __ldcg((const float4*)y + 2 * tid);       // pts 4t,4t+1
        float4 yb = __ldcg((const float4*)y + 2 * tid + 1);   // pts 4t+2,4t+3
        wey[2 * tid]     = make_float4(-ya.x, -ya.z, -ya.y, -ya.w);
        wey[2 * tid + 1] = make_float4(-yb.x, -yb.z, -yb.y, -yb.w);
        ((float4*)wex)[tid] = __ldcg((const float4*)g_v_log + tid);
    }
    __syncthreads();

    const size_t NM = (size_t)NN * NN;
    float* pi_out = out + 1;
    float* c_out  = out + 1 + NM;

    const float4 eA = wey[2 * tid];         // {-y0(4t),-y0(4t+1),-y1(4t),-y1(4t+1)}
    const float4 eB = wey[2 * tid + 1];
    const float4 vt4 = ((const float4*)wex)[tid];
    const ull nS2 = pk(-SCALEF, -SCALEF);
    ull ca = 0, cb = 0;

    for (int r = 0; r < RPC; ++r) {
        const int i = rbase + r;
        const float Xa = x[2 * i], Xb = x[2 * i + 1];
        const float ut = g_u_log[i];
        const ull Xap = pk(Xa, Xa), Xbp = pk(Xb, Xb);

        ull d0 = fadd2(Xap, pk(eA.x, eA.y));
        ull d1 = fadd2(Xbp, pk(eA.z, eA.w));
        float l0, h0, l1, h1; upk(d0, l0, h0); upk(d1, l1, h1);
        float ct0 = fabsf(l0) + fabsf(l1);
        float ct1 = fabsf(h0) + fabsf(h1);
        ull arg01 = ffma2(nS2, pk(ct0, ct1), pk(ut + vt4.x, ut + vt4.y));
        float a0, a1; upk(arg01, a0, a1);
        float p0 = ex2f(a0), p1 = ex2f(a1);

        ull d2 = fadd2(Xap, pk(eB.x, eB.y));
        ull d3 = fadd2(Xbp, pk(eB.z, eB.w));
        upk(d2, l0, h0); upk(d3, l1, h1);
        float ct2 = fabsf(l0) + fabsf(l1);
        float ct3 = fabsf(h0) + fabsf(h1);
        ull arg23 = ffma2(nS2, pk(ct2, ct3), pk(ut + vt4.z, ut + vt4.w));
        upk(arg23, a0, a1);
        float p2 = ex2f(a0), p3 = ex2f(a1);

        const size_t b = (size_t)i * NN + 4 * (size_t)tid;
        pi_out[b + 0] = p0; pi_out[b + 1] = p1; pi_out[b + 2] = p2; pi_out[b + 3] = p3;
        c_out[b + 0]  = ct0; c_out[b + 1] = ct1; c_out[b + 2] = ct2; c_out[b + 3] = ct3;
        ca = ffma2(pk(p0, p1), pk(ct0, ct1), ca);
        cb = ffma2(pk(p2, p3), pk(ct2, ct3), cb);
    }
    float cl, ch, dl, dh;
    upk(ca, cl, ch); upk(cb, dl, dh);
    float cacc = (cl + ch) + (dl + dh);
    #pragma unroll
    for (int o = 16; o > 0; o >>= 1) cacc += __shfl_xor_sync(0xffffffffu, cacc, o);
    if (lane == 0) red[wid] = cacc;
    __syncthreads();
    if (wid == 0) {
        float s = red[lane];
        #pragma unroll
        for (int o = 16; o > 0; o >>= 1) s += __shfl_xor_sync(0xffffffffu, s, o);
        if (lane == 0) {
            __stcg(&g_cost[cta], s);
            __threadfence();
            unsigned int old = atomicAdd(&g_costcnt, 1u);
            if (old == NCTA - 1) {
                __threadfence();
                float t = 0.f;
                for (int b = 0; b < NCTA; ++b) t += __ldcg(&g_cost[b]);
                out[0] = t;     // cost ** (1/P), P = 1
            }
        }
    }
}

extern "C" void kernel_launch(void* const* d_in, const int* in_sizes, int n_in,
                              void* d_out, int out_size) {
    (void)in_sizes; (void)n_in; (void)out_size;
    const float* x = (const float*)d_in[0];
    const float* y = (const float*)d_in[1];
    float* out = (float*)d_out;

    const size_t smem = 12288 * sizeof(float4);   // 192KB
    cudaFuncSetAttribute(sk_persist_kernel,
                         cudaFuncAttributeMaxDynamicSharedMemorySize, (int)smem);

    sk_init_kernel<<<8, 512>>>(x, y);
    sk_persist_kernel<<<NCTA, NT, smem>>>(x, y, out);
}